// round 3
// baseline (speedup 1.0000x reference)
#include <cuda_runtime.h>

// S4D as an exact diagonal state-space recurrence:
//   x[n,l] = w[n]*x[n,l-1] + u[l];  y[l] = 2*Re(sum_n Ct[n]*x[n,l]) + D*u[l]
//
// Round-3 layout: each warp processes FOUR (b,h) sequences; lane = (seq_local,
// mode_group j), each lane owns 4 modes (4j..4j+3) of its sequence. This packs
// 24 FMA-pipe ops per warp-step serving 4 sequence-steps, and amortizes the
// SHFL u-broadcast + STS partial-write across 4 sequences (smem traffic /4,
// which was the R2 binder: L1 throughput was 67.4%).

constexpr int Hh = 256;
constexpr int N2 = 32;
constexpr int Bb = 16;
constexpr int Ll = 8192;
constexpr int WPB = 4;            // warps per block
constexpr int SPW = 4;            // sequences per warp
constexpr int TILE = 32;
constexpr int SMSTRIDE = 36;      // floats per row: 16B-aligned, conflict-free STS

__global__ __launch_bounds__(WPB * 32, 1)
void s4d_scan4(const float* __restrict__ u,
               const float* __restrict__ log_dt,
               const float* __restrict__ log_A_real,
               const float* __restrict__ A_imag,
               const float* __restrict__ C,
               const float* __restrict__ D,
               float* __restrict__ y)
{
    __shared__ float sm[WPB][TILE][SMSTRIDE];

    const int warp = threadIdx.x >> 5;
    const int lane = threadIdx.x & 31;
    const int seq  = lane >> 3;          // which of the warp's 4 sequences
    const int j    = lane & 7;           // mode group within sequence

    const int g = (blockIdx.x * WPB + warp) * SPW + seq;   // g = b*H + h
    const int h = g & (Hh - 1);

    // ---- per-lane parameters: 4 modes n = 4j..4j+3 of head h ----
    const float dt = expf(log_dt[h]);
    const float d  = D[h];

    float wr[4], wi[4], nwi[4], Ctr[4], nCti[4], xr[4], xi[4];
    #pragma unroll
    for (int k = 0; k < 4; ++k) {
        const int n = 4 * j + k;
        const float ar = -expf(log_A_real[h * N2 + n]);
        const float ai = A_imag[h * N2 + n];
        const float mag = expf(ar * dt);
        wr[k]  = mag * cosf(ai * dt);
        wi[k]  = mag * sinf(ai * dt);
        nwi[k] = -wi[k];
        const float na = ar * ar + ai * ai;
        const float tr = wr[k] - 1.0f, ti = wi[k];
        const float qr = (tr * ar + ti * ai) / na;
        const float qi = (ti * ar - tr * ai) / na;
        const float cr = C[(h * N2 + n) * 2 + 0];
        const float ci = C[(h * N2 + n) * 2 + 1];
        Ctr[k]  =  2.0f * (cr * qr - ci * qi);
        nCti[k] = -2.0f * (cr * qi + ci * qr);
        xr[k] = 0.0f;
        xi[k] = 0.0f;
    }

    const float* __restrict__ up = u + (size_t)g * Ll;
    float*       __restrict__ yp = y + (size_t)g * Ll;

    for (int base = 0; base < Ll; base += TILE) {
        // lane (seq, j) holds u[base + 4j .. 4j+3] of ITS sequence (coalesced
        // 128B per 8-lane group). Also reused for the D*u term at reduction.
        const float4 uv = *reinterpret_cast<const float4*>(up + base + 4 * j);

        #pragma unroll
        for (int t = 0; t < TILE; ++t) {
            // broadcast u_t of this lane's sequence from the group lane
            // holding it: src = seq*8 + t/4, component t%4 (static: unrolled)
            const int src = (seq << 3) + (t >> 2);
            const float comp = (t & 3) == 0 ? uv.x
                             : (t & 3) == 1 ? uv.y
                             : (t & 3) == 2 ? uv.z : uv.w;
            const float ut = __shfl_sync(0xffffffffu, comp, src);

            #pragma unroll
            for (int k = 0; k < 4; ++k) {
                const float a  = fmaf(nwi[k], xi[k], ut);
                const float r  = fmaf(wr[k],  xr[k], a);
                const float im = fmaf(wi[k],  xr[k], wr[k] * xi[k]);
                xr[k] = r;
                xi[k] = im;
            }
            float p;
            p = fmaf(Ctr[0], xr[0], nCti[0] * xi[0]);
            p = fmaf(Ctr[1], xr[1], fmaf(nCti[1], xi[1], p));
            p = fmaf(Ctr[2], xr[2], fmaf(nCti[2], xi[2], p));
            p = fmaf(Ctr[3], xr[3], fmaf(nCti[3], xi[3], p));
            sm[warp][t][lane] = p;   // banks (4t+lane)%32: conflict-free
        }
        __syncwarp();

        // Reduction: lane (seq, j) produces outputs t = 4j..4j+3 of its
        // sequence: sum the 8 mode-group partials sm[t][seq*8 .. seq*8+7],
        // add D*u from the float4 already in registers, store STG.128.
        float4 out;
        float* o = &out.x;
        const float* uvp = &uv.x;
        #pragma unroll
        for (int q = 0; q < 4; ++q) {
            const int t2 = 4 * j + q;
            const float4* r4 =
                reinterpret_cast<const float4*>(&sm[warp][t2][seq * 8]);
            const float4 a = r4[0];
            const float4 b = r4[1];
            const float s = ((a.x + a.y) + (a.z + a.w))
                          + ((b.x + b.y) + (b.z + b.w));
            o[q] = fmaf(d, uvp[q], s);
        }
        *reinterpret_cast<float4*>(yp + base + 4 * j) = out;
        __syncwarp();
    }
}

extern "C" void kernel_launch(void* const* d_in, const int* in_sizes, int n_in,
                              void* d_out, int out_size)
{
    const float* u          = (const float*)d_in[0];
    const float* log_dt     = (const float*)d_in[1];
    const float* log_A_real = (const float*)d_in[2];
    const float* A_imag     = (const float*)d_in[3];
    const float* C          = (const float*)d_in[4];
    const float* D          = (const float*)d_in[5];
    float* y = (float*)d_out;

    const int seqs  = Bb * Hh;                 // 4096 sequences
    const int grid  = seqs / (WPB * SPW);      // 256 blocks of 4 warps
    s4d_scan4<<<grid, WPB * 32>>>(u, log_dt, log_A_real, A_imag, C, D, y);
}

// round 4
// speedup vs baseline: 1.2831x; 1.2831x over previous
#include <cuda_runtime.h>

// S4D as exact diagonal recurrence, R4: 2 sequences per warp, 2 modes per lane
// packed with Blackwell f32x2 FMAs.
//   lane = (seq s in [0,2), j in [0,16));  lane owns modes {2j, 2j+1} of seq s.
//   State update: 4 x fma.rn.f32x2 per step covering both modes.
//   Projection:   2 packed ops + 1 horizontal add -> scalar partial p.
//   Per-tile (32 steps) smem transpose: lane (s,j) reduces outputs j and j+16.

constexpr int Hh = 256;
constexpr int N2 = 32;
constexpr int Bb = 16;
constexpr int Ll = 8192;
constexpr int WPB  = 2;       // warps per block (small blocks -> even SM balance)
constexpr int TILE = 32;
constexpr int STR  = 36;      // row stride (floats): 16B-aligned, conflict-free

using u64 = unsigned long long;

__device__ __forceinline__ u64 pack2(float lo, float hi) {
    u64 r;
    asm("mov.b64 %0, {%1, %2};" : "=l"(r) : "f"(lo), "f"(hi));
    return r;
}
__device__ __forceinline__ void unpack2(u64 v, float& lo, float& hi) {
    asm("mov.b64 {%0, %1}, %2;" : "=f"(lo), "=f"(hi) : "l"(v));
}
__device__ __forceinline__ u64 fma2(u64 a, u64 b, u64 c) {
    u64 d;
    asm("fma.rn.f32x2 %0, %1, %2, %3;" : "=l"(d) : "l"(a), "l"(b), "l"(c));
    return d;
}
__device__ __forceinline__ u64 mul2(u64 a, u64 b) {
    u64 d;
    asm("mul.rn.f32x2 %0, %1, %2;" : "=l"(d) : "l"(a), "l"(b));
    return d;
}

__global__ __launch_bounds__(WPB * 32, 1)
void s4d_pack2(const float* __restrict__ u,
               const float* __restrict__ log_dt,
               const float* __restrict__ log_A_real,
               const float* __restrict__ A_imag,
               const float* __restrict__ C,
               const float* __restrict__ D,
               float* __restrict__ y)
{
    __shared__ float sm[WPB][TILE][STR];

    const int warp = threadIdx.x >> 5;
    const int lane = threadIdx.x & 31;
    const int s    = lane >> 4;            // which of the warp's 2 sequences
    const int j    = lane & 15;            // mode-pair index / output index

    const int W = blockIdx.x * WPB + warp; // global warp id
    const int g = 2 * W + s;               // g = b*H + h
    const int h = g & (Hh - 1);

    // ---- per-lane parameters for modes n = 2j, 2j+1 of head h ----
    const float dt = expf(log_dt[h]);
    const float d  = D[h];

    float wr[2], wi[2], Ctr[2], nCti[2];
    #pragma unroll
    for (int k = 0; k < 2; ++k) {
        const int n = 2 * j + k;
        const float ar = -expf(log_A_real[h * N2 + n]);
        const float ai = A_imag[h * N2 + n];
        const float mag = expf(ar * dt);
        wr[k] = mag * cosf(ai * dt);
        wi[k] = mag * sinf(ai * dt);
        const float na = ar * ar + ai * ai;
        const float tr = wr[k] - 1.0f, ti = wi[k];
        const float qr = (tr * ar + ti * ai) / na;
        const float qi = (ti * ar - tr * ai) / na;
        const float cr = C[(h * N2 + n) * 2 + 0];
        const float ci = C[(h * N2 + n) * 2 + 1];
        Ctr[k]  =  2.0f * (cr * qr - ci * qi);
        nCti[k] = -2.0f * (cr * qi + ci * qr);
    }
    const u64 WR2   = pack2(wr[0],   wr[1]);
    const u64 WI2   = pack2(wi[0],   wi[1]);
    const u64 NWI2  = pack2(-wi[0], -wi[1]);
    const u64 CTR2  = pack2(Ctr[0],  Ctr[1]);
    const u64 NCTI2 = pack2(nCti[0], nCti[1]);

    u64 XR = pack2(0.0f, 0.0f);
    u64 XI = pack2(0.0f, 0.0f);

    const float* __restrict__ up = u + (size_t)g * Ll;
    float*       __restrict__ yp = y + (size_t)g * Ll;

    for (int base = 0; base < Ll; base += TILE) {
        // lane (s,j) holds u[base+j] and u[base+j+16] of its sequence:
        // used both as the SHFL broadcast source and for the D*u term.
        const float u_lo = up[base + j];
        const float u_hi = up[base + j + 16];

        #pragma unroll
        for (int t = 0; t < TILE; ++t) {
            // u_t of this lane's sequence lives in lane (s*16 + (t&15)),
            // component lo for t<16, hi for t>=16 (all static, unrolled).
            const float src = (t < 16) ? u_lo : u_hi;
            const float ut  = __shfl_sync(0xffffffffu, src,
                                          (lane & 16) | (t & 15));
            const u64 U2 = pack2(ut, ut);

            // complex state update, 2 modes packed:
            const u64 t1  = fma2(NWI2, XI, U2);
            const u64 nXR = fma2(WR2,  XR, t1);
            const u64 t2  = mul2(WR2,  XI);
            XI = fma2(WI2, XR, t2);
            XR = nXR;

            // projection partial: p = sum_k (Ctr*xr + nCti*xi)
            u64 q = mul2(CTR2, XR);
            q = fma2(NCTI2, XI, q);
            float qlo, qhi;
            unpack2(q, qlo, qhi);
            sm[warp][t][lane] = qlo + qhi;   // conflict-free (consecutive lanes)
        }
        __syncwarp();

        // lane (s,j) reduces outputs t=j and t=j+16 of its sequence:
        // 16 partials each at sm[warp][t][16*s .. 16*s+15] (4x LDS.128,
        // bank-disjoint across lanes since 4*t mod 32 is distinct per phase).
        {
            const float4* r0 = reinterpret_cast<const float4*>(&sm[warp][j][16 * s]);
            const float4 a0 = r0[0], a1 = r0[1], a2 = r0[2], a3 = r0[3];
            const float s0 = (((a0.x + a0.y) + (a0.z + a0.w))
                            + ((a1.x + a1.y) + (a1.z + a1.w)))
                           + (((a2.x + a2.y) + (a2.z + a2.w))
                            + ((a3.x + a3.y) + (a3.z + a3.w)));
            yp[base + j] = fmaf(d, u_lo, s0);

            const float4* r1 = reinterpret_cast<const float4*>(&sm[warp][j + 16][16 * s]);
            const float4 b0 = r1[0], b1 = r1[1], b2 = r1[2], b3 = r1[3];
            const float s1 = (((b0.x + b0.y) + (b0.z + b0.w))
                            + ((b1.x + b1.y) + (b1.z + b1.w)))
                           + (((b2.x + b2.y) + (b2.z + b2.w))
                            + ((b3.x + b3.y) + (b3.z + b3.w)));
            yp[base + j + 16] = fmaf(d, u_hi, s1);
        }
        __syncwarp();
    }
}

extern "C" void kernel_launch(void* const* d_in, const int* in_sizes, int n_in,
                              void* d_out, int out_size)
{
    const float* u          = (const float*)d_in[0];
    const float* log_dt     = (const float*)d_in[1];
    const float* log_A_real = (const float*)d_in[2];
    const float* A_imag     = (const float*)d_in[3];
    const float* C          = (const float*)d_in[4];
    const float* D          = (const float*)d_in[5];
    float* y = (float*)d_out;

    const int seqs = Bb * Hh;                    // 4096 sequences
    const int grid = seqs / (2 * WPB);           // 1024 blocks of 2 warps
    s4d_pack2<<<grid, WPB * 32>>>(u, log_dt, log_A_real, A_imag, C, D, y);
}

// round 5
// speedup vs baseline: 1.3489x; 1.0513x over previous
#include <cuda_runtime.h>

// S4D exact diagonal recurrence. R5 = R4 (2 seqs/warp, 2 packed modes/lane,
// f32x2 FMAs) + double-buffered u-tile prefetch. R4's issue stalled at 41%
// because each tile's LDG of u was consumed immediately (DRAM ~580cyc exposed
// once per 32-step tile). Prefetching tile i+1 during tile i hides it.

constexpr int Hh = 256;
constexpr int N2 = 32;
constexpr int Bb = 16;
constexpr int Ll = 8192;
constexpr int WPB  = 2;
constexpr int TILE = 32;
constexpr int STR  = 36;

using u64 = unsigned long long;

__device__ __forceinline__ u64 pack2(float lo, float hi) {
    u64 r;
    asm("mov.b64 %0, {%1, %2};" : "=l"(r) : "f"(lo), "f"(hi));
    return r;
}
__device__ __forceinline__ void unpack2(u64 v, float& lo, float& hi) {
    asm("mov.b64 {%0, %1}, %2;" : "=f"(lo), "=f"(hi) : "l"(v));
}
__device__ __forceinline__ u64 fma2(u64 a, u64 b, u64 c) {
    u64 d;
    asm("fma.rn.f32x2 %0, %1, %2, %3;" : "=l"(d) : "l"(a), "l"(b), "l"(c));
    return d;
}
__device__ __forceinline__ u64 mul2(u64 a, u64 b) {
    u64 d;
    asm("mul.rn.f32x2 %0, %1, %2;" : "=l"(d) : "l"(a), "l"(b));
    return d;
}

__global__ __launch_bounds__(WPB * 32, 1)
void s4d_pack2_pf(const float* __restrict__ u,
                  const float* __restrict__ log_dt,
                  const float* __restrict__ log_A_real,
                  const float* __restrict__ A_imag,
                  const float* __restrict__ C,
                  const float* __restrict__ D,
                  float* __restrict__ y)
{
    __shared__ float sm[WPB][TILE][STR];

    const int warp = threadIdx.x >> 5;
    const int lane = threadIdx.x & 31;
    const int s    = lane >> 4;            // which of the warp's 2 sequences
    const int j    = lane & 15;            // mode-pair index / output column

    const int W = blockIdx.x * WPB + warp;
    const int g = 2 * W + s;               // g = b*H + h
    const int h = g & (Hh - 1);

    // ---- per-lane parameters for modes n = 2j, 2j+1 of head h ----
    const float dt = expf(log_dt[h]);
    const float d  = D[h];

    float wr[2], wi[2], Ctr[2], nCti[2];
    #pragma unroll
    for (int k = 0; k < 2; ++k) {
        const int n = 2 * j + k;
        const float ar = -expf(log_A_real[h * N2 + n]);
        const float ai = A_imag[h * N2 + n];
        const float mag = expf(ar * dt);
        wr[k] = mag * cosf(ai * dt);
        wi[k] = mag * sinf(ai * dt);
        const float na = ar * ar + ai * ai;
        const float tr = wr[k] - 1.0f, ti = wi[k];
        const float qr = (tr * ar + ti * ai) / na;
        const float qi = (ti * ar - tr * ai) / na;
        const float cr = C[(h * N2 + n) * 2 + 0];
        const float ci = C[(h * N2 + n) * 2 + 1];
        Ctr[k]  =  2.0f * (cr * qr - ci * qi);
        nCti[k] = -2.0f * (cr * qi + ci * qr);
    }
    const u64 WR2   = pack2(wr[0],   wr[1]);
    const u64 WI2   = pack2(wi[0],   wi[1]);
    const u64 NWI2  = pack2(-wi[0], -wi[1]);
    const u64 CTR2  = pack2(Ctr[0],  Ctr[1]);
    const u64 NCTI2 = pack2(nCti[0], nCti[1]);

    u64 XR = pack2(0.0f, 0.0f);
    u64 XI = pack2(0.0f, 0.0f);

    const float* __restrict__ up = u + (size_t)g * Ll;
    float*       __restrict__ yp = y + (size_t)g * Ll;

    // lane (s,j) holds u[base+2j], u[base+2j+1] of its sequence as a float2:
    // one 128B segment per sequence per tile (coalesced LDG.64).
    float2 uv = *reinterpret_cast<const float2*>(up + 2 * j);

    for (int base = 0; base < Ll; base += TILE) {
        // prefetch next tile's u while this tile computes (covers DRAM lat)
        float2 uv_next;
        {
            const int nb = (base + TILE < Ll) ? (base + TILE) : 0;
            uv_next = *reinterpret_cast<const float2*>(up + nb + 2 * j);
        }

        #pragma unroll
        for (int t = 0; t < TILE; ++t) {
            // u_t of this lane's sequence: lane (s*16 + t/2), comp t&1
            const float src = (t & 1) ? uv.y : uv.x;
            const float ut  = __shfl_sync(0xffffffffu, src,
                                          (lane & 16) | (t >> 1));
            const u64 U2 = pack2(ut, ut);

            const u64 t1  = fma2(NWI2, XI, U2);
            const u64 nXR = fma2(WR2,  XR, t1);
            const u64 t2  = mul2(WR2,  XI);
            XI = fma2(WI2, XR, t2);
            XR = nXR;

            u64 q = mul2(CTR2, XR);
            q = fma2(NCTI2, XI, q);
            float qlo, qhi;
            unpack2(q, qlo, qhi);
            sm[warp][t][lane] = qlo + qhi;   // conflict-free
        }
        __syncwarp();

        // lane (s,j) reduces outputs t = 2j, 2j+1 of its sequence and
        // stores them as one STG.64.
        {
            float2 out;
            #pragma unroll
            for (int q2 = 0; q2 < 2; ++q2) {
                const int t2 = 2 * j + q2;
                const float4* r4 =
                    reinterpret_cast<const float4*>(&sm[warp][t2][16 * s]);
                const float4 a0 = r4[0], a1 = r4[1], a2 = r4[2], a3 = r4[3];
                const float sum = (((a0.x + a0.y) + (a0.z + a0.w))
                                 + ((a1.x + a1.y) + (a1.z + a1.w)))
                                + (((a2.x + a2.y) + (a2.z + a2.w))
                                 + ((a3.x + a3.y) + (a3.z + a3.w)));
                (&out.x)[q2] = fmaf(d, q2 ? uv.y : uv.x, sum);
            }
            *reinterpret_cast<float2*>(yp + base + 2 * j) = out;
        }
        __syncwarp();

        uv = uv_next;
    }
}

extern "C" void kernel_launch(void* const* d_in, const int* in_sizes, int n_in,
                              void* d_out, int out_size)
{
    const float* u          = (const float*)d_in[0];
    const float* log_dt     = (const float*)d_in[1];
    const float* log_A_real = (const float*)d_in[2];
    const float* A_imag     = (const float*)d_in[3];
    const float* C          = (const float*)d_in[4];
    const float* D          = (const float*)d_in[5];
    float* y = (float*)d_out;

    const int seqs = Bb * Hh;
    const int grid = seqs / (2 * WPB);           // 1024 blocks, 2 warps each
    s4d_pack2_pf<<<grid, WPB * 32>>>(u, log_dt, log_A_real, A_imag, C, D, y);
}